// round 2
// baseline (speedup 1.0000x reference)
#include <cuda_runtime.h>
#include <cuda_bf16.h>

// Scratch (allocation-free per harness rules): cross-CTA staging for the
// last-block finisher pattern.
__device__ float        g_tileSx[64];
__device__ float        g_tileSy[64];
__device__ float        g_partial[64];
__device__ unsigned int g_count = 0;

__device__ __forceinline__ float ssim_term(float mx, float my) {
    const float c1 = 0.2f;
    return 1.0f - (2.0f * mx * my + c1) / (mx * mx + my * my + c1);
}

// 64 CTAs, each owns a 32x32 tile. 256 threads/CTA, each owns a 2x2 pixel quad.
// Depths (block side h = 256>>d), weight W_d = 0.25^d * K_LOSS[d]:
//   d=8 h=1   W=1/65536      per-pixel           (registers)
//   d=7 h=2   W=2/16384      per-quad            (registers)
//   d=6 h=4   W=3/4096       8x8 nodes/CTA       (smem)
//   d=5 h=8   W=4/1024       4x4 nodes/CTA       (smem)
//   d=4 h=16  W=5/256        2x2 nodes/CTA       (smem)
//   d=3 h=32  W=6/64         1 node/CTA          (smem)
//   d=2 h=64  W=7/16         4x4 global          (finisher CTA)
//   d=1 h=128 W=2            2x2 global          (finisher CTA)
//   d=0 h=256 W=9            1 node              (finisher CTA)
__global__ void loss_quadtree_kernel(const float* __restrict__ x,
                                     const float* __restrict__ y,
                                     float* __restrict__ out) {
    __shared__ float sX[256];
    __shared__ float sY[256];
    __shared__ float sL[256];
    __shared__ int   sLast;

    const int t   = threadIdx.x;
    const int bid = blockIdx.x;
    const int tx  = bid & 7, ty = bid >> 3;     // tile coords in 8x8 grid
    const int qx  = t & 15,  qy = t >> 4;       // quad coords in 16x16 grid
    const int r   = ty * 32 + qy * 2;
    const int c   = tx * 32 + qx * 2;

    const float2* x2 = (const float2*)x;
    const float2* y2 = (const float2*)y;
    const int i0 = (r * 256 + c) >> 1;
    const int i1 = ((r + 1) * 256 + c) >> 1;
    float2 xa = x2[i0], xb = x2[i1];
    float2 ya = y2[i0], yb = y2[i1];

    float acc = 0.0f;

    // d=8: per-pixel (h=1 -> mu = pixel)
    acc += (1.0f / 65536.0f) *
           (ssim_term(xa.x, ya.x) + ssim_term(xa.y, ya.y) +
            ssim_term(xb.x, yb.x) + ssim_term(xb.y, yb.y));

    // d=7: this thread's 2x2 quad (h=2)
    float Sx = xa.x + xa.y + xb.x + xb.y;
    float Sy = ya.x + ya.y + yb.x + yb.y;
    acc += (2.0f / 16384.0f) * ssim_term(Sx * 0.5f, Sy * 0.5f);

    sX[t] = Sx; sY[t] = Sy;
    __syncthreads();

    // d=6: 8x8 nodes, h=4 (threads 0..63 gather from 16-wide layout)
    float S4x = 0.0f, S4y = 0.0f;
    if (t < 64) {
        int nx = t & 7, ny = t >> 3;
        int b = (ny * 2) * 16 + nx * 2;
        S4x = sX[b] + sX[b + 1] + sX[b + 16] + sX[b + 17];
        S4y = sY[b] + sY[b + 1] + sY[b + 16] + sY[b + 17];
        acc += (3.0f / 4096.0f) * ssim_term(S4x * 0.25f, S4y * 0.25f);
    }
    __syncthreads();
    if (t < 64) { sX[t] = S4x; sY[t] = S4y; }
    __syncthreads();

    // d=5: 4x4 nodes, h=8 (threads 0..15 gather from 8-wide layout)
    float S8x = 0.0f, S8y = 0.0f;
    if (t < 16) {
        int nx = t & 3, ny = t >> 2;
        int b = (ny * 2) * 8 + nx * 2;
        S8x = sX[b] + sX[b + 1] + sX[b + 8] + sX[b + 9];
        S8y = sY[b] + sY[b + 1] + sY[b + 8] + sY[b + 9];
        acc += (4.0f / 1024.0f) * ssim_term(S8x * 0.125f, S8y * 0.125f);
    }
    __syncthreads();
    if (t < 16) { sX[t] = S8x; sY[t] = S8y; }
    __syncthreads();

    // d=4: 2x2 nodes, h=16 (threads 0..3 gather from 4-wide layout)
    float S16x = 0.0f, S16y = 0.0f;
    if (t < 4) {
        int nx = t & 1, ny = t >> 1;
        int b = (ny * 2) * 4 + nx * 2;
        S16x = sX[b] + sX[b + 1] + sX[b + 4] + sX[b + 5];
        S16y = sY[b] + sY[b + 1] + sY[b + 4] + sY[b + 5];
        acc += (5.0f / 256.0f) * ssim_term(S16x * (1.0f / 16.0f),
                                           S16y * (1.0f / 16.0f));
    }
    __syncthreads();
    if (t < 4) { sX[t] = S16x; sY[t] = S16y; }
    __syncthreads();

    // d=3: one node per CTA, h=32
    float S32x = 0.0f, S32y = 0.0f;
    if (t == 0) {
        S32x = sX[0] + sX[1] + sX[2] + sX[3];
        S32y = sY[0] + sY[1] + sY[2] + sY[3];
        acc += (6.0f / 64.0f) * ssim_term(S32x * (1.0f / 32.0f),
                                          S32y * (1.0f / 32.0f));
    }
    __syncthreads();

    // Deterministic per-CTA loss tree reduction
    sL[t] = acc;
    __syncthreads();
    #pragma unroll
    for (int s = 128; s > 0; s >>= 1) {
        if (t < s) sL[t] += sL[t + s];
        __syncthreads();
    }

    if (t == 0) {
        g_partial[bid] = sL[0];
        g_tileSx[bid]  = S32x;
        g_tileSy[bid]  = S32y;
        __threadfence();
        unsigned old = atomicAdd(&g_count, 1u);
        sLast = (old == 63u) ? 1 : 0;
    }
    __syncthreads();

    // Last CTA to arrive finishes depths 2..0 + global sum (deterministic order)
    if (sLast && t == 0) {
        g_count = 0;  // reset for next graph replay

        volatile float* vp = g_partial;
        volatile float* vx = g_tileSx;
        volatile float* vy = g_tileSy;

        float total = 0.0f;
        #pragma unroll
        for (int i = 0; i < 64; i++) total += vp[i];

        float lx[64], ly[64];
        #pragma unroll
        for (int i = 0; i < 64; i++) { lx[i] = vx[i]; ly[i] = vy[i]; }

        // d=2: 4x4 nodes, h=64 (pool 8x8 tile grid)
        float mx[16], my[16];
        #pragma unroll
        for (int ny = 0; ny < 4; ny++)
            #pragma unroll
            for (int nx = 0; nx < 4; nx++) {
                int b = (ny * 2) * 8 + nx * 2;
                float sx = lx[b] + lx[b + 1] + lx[b + 8] + lx[b + 9];
                float sy = ly[b] + ly[b + 1] + ly[b + 8] + ly[b + 9];
                mx[ny * 4 + nx] = sx; my[ny * 4 + nx] = sy;
                total += (7.0f / 16.0f) * ssim_term(sx * (1.0f / 64.0f),
                                                    sy * (1.0f / 64.0f));
            }

        // d=1: 2x2 nodes, h=128
        float px[4], py[4];
        #pragma unroll
        for (int ny = 0; ny < 2; ny++)
            #pragma unroll
            for (int nx = 0; nx < 2; nx++) {
                int b = (ny * 2) * 4 + nx * 2;
                float sx = mx[b] + mx[b + 1] + mx[b + 4] + mx[b + 5];
                float sy = my[b] + my[b + 1] + my[b + 4] + my[b + 5];
                px[ny * 2 + nx] = sx; py[ny * 2 + nx] = sy;
                total += 2.0f * ssim_term(sx * (1.0f / 128.0f),
                                          sy * (1.0f / 128.0f));
            }

        // d=0: root, h=256
        float sx = px[0] + px[1] + px[2] + px[3];
        float sy = py[0] + py[1] + py[2] + py[3];
        total += 9.0f * ssim_term(sx * (1.0f / 256.0f), sy * (1.0f / 256.0f));

        out[0] = total;
    }
}

extern "C" void kernel_launch(void* const* d_in, const int* in_sizes, int n_in,
                              void* d_out, int out_size) {
    const float* x = (const float*)d_in[0];   // input  (256x256 f32)
    const float* y = (const float*)d_in[1];   // target (256x256 f32)
    float* out = (float*)d_out;               // scalar f32
    loss_quadtree_kernel<<<64, 256>>>(x, y, out);
}

// round 3
// speedup vs baseline: 1.1033x; 1.1033x over previous
#include <cuda_runtime.h>

// Cross-CTA staging for the last-block finisher pattern (allocation-free).
__device__ float        g_tileSx[64];
__device__ float        g_tileSy[64];
__device__ float        g_partial[64];
__device__ unsigned int g_count = 0;

#define FULL 0xffffffffu

__device__ __forceinline__ float ssim_term(float mx, float my) {
    const float c1 = 0.2f;
    return 1.0f - (2.0f * mx * my + c1) / (mx * mx + my * my + c1);
}

// 64 CTAs, each owns a 32x32 tile; 256 threads (8 warps), each thread a 2x2 quad.
// Warp w holds quad-rows 2w and 2w+1 (lane<16 -> row 2w, lane>=16 -> row 2w+1).
// Depth weights W_d = 0.25^d * K_LOSS[d]:
//   d=8: 1/65536  d=7: 2/16384  d=6: 3/4096  d=5: 4/1024  d=4: 5/256
//   d=3: 6/64     d=2: 7/16     d=1: 2       d=0: 9
__global__ __launch_bounds__(256, 1)
void loss_quadtree_kernel(const float* __restrict__ x,
                          const float* __restrict__ y,
                          float* __restrict__ out) {
    __shared__ float n4x[64];   // d=6 node sums (8x8 grid per CTA)
    __shared__ float n4y[64];
    __shared__ float accW[8];   // per-warp loss partials

    const int t    = threadIdx.x;
    const int lane = t & 31;
    const int w    = t >> 5;
    const int bid  = blockIdx.x;
    const int tx   = bid & 7, ty = bid >> 3;     // tile in 8x8 grid
    const int qx   = lane & 15;
    const int qy   = 2 * w + (lane >> 4);
    const int r    = ty * 32 + qy * 2;
    const int c    = tx * 32 + qx * 2;

    const float2* x2 = (const float2*)x;
    const float2* y2 = (const float2*)y;
    const int i0 = (r * 256 + c) >> 1;
    const int i1 = ((r + 1) * 256 + c) >> 1;
    float2 xa = x2[i0], xb = x2[i1];
    float2 ya = y2[i0], yb = y2[i1];

    // d=8 (per-pixel) + d=7 (per-quad), in registers
    float acc = (1.0f / 65536.0f) *
                (ssim_term(xa.x, ya.x) + ssim_term(xa.y, ya.y) +
                 ssim_term(xb.x, yb.x) + ssim_term(xb.y, yb.y));
    float Sx = xa.x + xa.y + xb.x + xb.y;
    float Sy = ya.x + ya.y + yb.x + yb.y;
    acc += (2.0f / 16384.0f) * ssim_term(Sx * 0.5f, Sy * 0.5f);

    // d=6 via shuffles: combine row pair (lane +16) then column pair (lane +1)
    float ax = Sx + __shfl_down_sync(FULL, Sx, 16);
    float ay = Sy + __shfl_down_sync(FULL, Sy, 16);
    float S4x = ax + __shfl_down_sync(FULL, ax, 1);
    float S4y = ay + __shfl_down_sync(FULL, ay, 1);
    if (lane < 16 && !(lane & 1)) {
        acc += (3.0f / 4096.0f) * ssim_term(S4x * 0.25f, S4y * 0.25f);
        int idx = w * 8 + (lane >> 1);   // node (row=w, col=qx/2)
        n4x[idx] = S4x;
        n4y[idx] = S4y;
    }

    // Per-warp loss reduction (deterministic xor butterfly)
    #pragma unroll
    for (int o = 16; o > 0; o >>= 1) acc += __shfl_xor_sync(FULL, acc, o);
    if (lane == 0) accW[w] = acc;

    __syncthreads();              // the only CTA-wide barrier
    if (w != 0) return;           // warps 1..7 retire

    // ---- warp 0: d=5..3 from the 8x8 node grid in smem ----
    float acc2 = 0.0f, S8x = 0.0f, S8y = 0.0f;
    if (lane < 16) {
        int ny = lane >> 2, nx = lane & 3;       // 4x4 d=5 node grid
        int b = ny * 16 + nx * 2;                // (2ny)*8 + 2nx
        S8x = n4x[b] + n4x[b + 1] + n4x[b + 8] + n4x[b + 9];
        S8y = n4y[b] + n4y[b + 1] + n4y[b + 8] + n4y[b + 9];
        acc2 = (4.0f / 1024.0f) * ssim_term(S8x * 0.125f, S8y * 0.125f);
    }
    if (lane < 8) acc2 += accW[lane];

    // d=4: lanes {0,2,8,10} of the 4x4 grid
    float bx = S8x + __shfl_down_sync(FULL, S8x, 1);
    float by = S8y + __shfl_down_sync(FULL, S8y, 1);
    float S16x = bx + __shfl_down_sync(FULL, bx, 4);
    float S16y = by + __shfl_down_sync(FULL, by, 4);
    if (lane == 0 || lane == 2 || lane == 8 || lane == 10)
        acc2 += (5.0f / 256.0f) *
                ssim_term(S16x * (1.0f / 16.0f), S16y * (1.0f / 16.0f));

    // d=3: lane 0
    float cx = S16x + __shfl_down_sync(FULL, S16x, 2);
    float cy = S16y + __shfl_down_sync(FULL, S16y, 2);
    float S32x = cx + __shfl_down_sync(FULL, cx, 8);
    float S32y = cy + __shfl_down_sync(FULL, cy, 8);
    if (lane == 0)
        acc2 += (6.0f / 64.0f) *
                ssim_term(S32x * (1.0f / 32.0f), S32y * (1.0f / 32.0f));

    #pragma unroll
    for (int o = 16; o > 0; o >>= 1) acc2 += __shfl_xor_sync(FULL, acc2, o);

    int last = 0;
    if (lane == 0) {
        g_partial[bid] = acc2;
        g_tileSx[bid]  = S32x;
        g_tileSy[bid]  = S32y;
        __threadfence();
        unsigned old = atomicAdd(&g_count, 1u);
        last = (old == 63u) ? 1 : 0;
    }
    last = __shfl_sync(FULL, last, 0);
    if (!last) return;

    // ---- finisher: warp 0 of the last-arriving CTA, all 32 lanes ----
    if (lane == 0) g_count = 0;   // reset for next graph replay

    // Sum of all 64 CTA partials (2 per lane, xor butterfly)
    float ftot = __ldcg(&g_partial[lane]) + __ldcg(&g_partial[lane + 32]);

    // d=2: 16 nodes over the 8x8 tile grid, one per lane<16 (parallel L2 loads)
    float S64x = 0.0f, S64y = 0.0f;
    if (lane < 16) {
        int ny = lane >> 2, nx = lane & 3;
        int b = ny * 16 + nx * 2;
        S64x = __ldcg(&g_tileSx[b])     + __ldcg(&g_tileSx[b + 1]) +
               __ldcg(&g_tileSx[b + 8]) + __ldcg(&g_tileSx[b + 9]);
        S64y = __ldcg(&g_tileSy[b])     + __ldcg(&g_tileSy[b + 1]) +
               __ldcg(&g_tileSy[b + 8]) + __ldcg(&g_tileSy[b + 9]);
        ftot += (7.0f / 16.0f) *
                ssim_term(S64x * (1.0f / 64.0f), S64y * (1.0f / 64.0f));
    }

    // d=1: lanes {0,2,8,10}
    float dx = S64x + __shfl_down_sync(FULL, S64x, 1);
    float dy = S64y + __shfl_down_sync(FULL, S64y, 1);
    float S128x = dx + __shfl_down_sync(FULL, dx, 4);
    float S128y = dy + __shfl_down_sync(FULL, dy, 4);
    if (lane == 0 || lane == 2 || lane == 8 || lane == 10)
        ftot += 2.0f *
                ssim_term(S128x * (1.0f / 128.0f), S128y * (1.0f / 128.0f));

    // d=0: lane 0
    float ex = S128x + __shfl_down_sync(FULL, S128x, 2);
    float ey = S128y + __shfl_down_sync(FULL, S128y, 2);
    float S256x = ex + __shfl_down_sync(FULL, ex, 8);
    float S256y = ey + __shfl_down_sync(FULL, ey, 8);
    if (lane == 0)
        ftot += 9.0f *
                ssim_term(S256x * (1.0f / 256.0f), S256y * (1.0f / 256.0f));

    #pragma unroll
    for (int o = 16; o > 0; o >>= 1) ftot += __shfl_xor_sync(FULL, ftot, o);

    if (lane == 0) out[0] = ftot;
}

extern "C" void kernel_launch(void* const* d_in, const int* in_sizes, int n_in,
                              void* d_out, int out_size) {
    const float* x = (const float*)d_in[0];   // input  (256x256 f32)
    const float* y = (const float*)d_in[1];   // target (256x256 f32)
    float* out = (float*)d_out;               // scalar f32
    loss_quadtree_kernel<<<64, 256>>>(x, y, out);
}

// round 6
// speedup vs baseline: 1.1157x; 1.0112x over previous
#include <cuda_runtime.h>

// Cross-CTA staging (allocation-free): 16 tiles.
__device__ float        g_tileSx[16];
__device__ float        g_tileSy[16];
__device__ float        g_partial[16];
__device__ unsigned int g_count = 0;

#define FULL 0xffffffffu

// fast ssim loss term: 1 - (2 m_x m_y + c1)/(m_x^2 + m_y^2 + c1)
__device__ __forceinline__ float ssim_term(float mx, float my) {
    const float c1 = 0.2f;
    return 1.0f - __fdividef(2.0f * mx * my + c1,
                             mx * mx + my * my + c1);
}

// 16 CTAs (4x4 grid of 64x64 tiles), 256 threads each.
// Thread owns a 4x4 pixel block (one d=6 node) loaded as 4 float4 per tensor.
// Warp w holds block-rows 2w (lane<16) and 2w+1 (lane>=16) of the 16x16 grid.
// Depth weights W_d = 0.25^d * K_LOSS[d]:
//   d=8: 1/65536  d=7: 2/16384  d=6: 3/4096  d=5: 4/1024  d=4: 5/256
//   d=3: 6/64     d=2: 7/16     d=1: 2       d=0: 9
__global__ __launch_bounds__(256, 1)
void loss_quadtree_kernel(const float* __restrict__ x,
                          const float* __restrict__ y,
                          float* __restrict__ out) {
    __shared__ float n8x[64];   // d=5 node sums (8x8 grid per CTA)
    __shared__ float n8y[64];
    __shared__ float accW[8];   // per-warp loss partials

    const int t    = threadIdx.x;
    const int lane = t & 31;
    const int w    = t >> 5;
    const int bid  = blockIdx.x;
    const int tx   = bid & 3, ty = bid >> 2;       // tile in 4x4 grid
    const int qx   = lane & 15;                    // block col (0..15)
    const int qy   = 2 * w + (lane >> 4);          // block row (0..15)
    const int r    = ty * 64 + qy * 4;
    const int c    = tx * 64 + qx * 4;

    // 8 x LDG.128 issued up front (MLP=8)
    const float4* x4 = (const float4*)x;
    const float4* y4 = (const float4*)y;
    const int base = r * 64 + (c >> 2);            // row stride = 256/4
    float4 xr0 = x4[base],        xr1 = x4[base + 64];
    float4 xr2 = x4[base + 128],  xr3 = x4[base + 192];
    float4 yr0 = y4[base],        yr1 = y4[base + 64];
    float4 yr2 = y4[base + 128],  yr3 = y4[base + 192];

    // d=8: 16 per-pixel terms
    float s8 =
        ssim_term(xr0.x, yr0.x) + ssim_term(xr0.y, yr0.y) +
        ssim_term(xr0.z, yr0.z) + ssim_term(xr0.w, yr0.w) +
        ssim_term(xr1.x, yr1.x) + ssim_term(xr1.y, yr1.y) +
        ssim_term(xr1.z, yr1.z) + ssim_term(xr1.w, yr1.w) +
        ssim_term(xr2.x, yr2.x) + ssim_term(xr2.y, yr2.y) +
        ssim_term(xr2.z, yr2.z) + ssim_term(xr2.w, yr2.w) +
        ssim_term(xr3.x, yr3.x) + ssim_term(xr3.y, yr3.y) +
        ssim_term(xr3.z, yr3.z) + ssim_term(xr3.w, yr3.w);
    float acc = (1.0f / 65536.0f) * s8;

    // d=7: 4 quad (2x2) sums
    float qxa = xr0.x + xr0.y + xr1.x + xr1.y;   // quad (0,0)
    float qxb = xr0.z + xr0.w + xr1.z + xr1.w;   // quad (0,1)
    float qxc = xr2.x + xr2.y + xr3.x + xr3.y;   // quad (1,0)
    float qxd = xr2.z + xr2.w + xr3.z + xr3.w;   // quad (1,1)
    float qya = yr0.x + yr0.y + yr1.x + yr1.y;
    float qyb = yr0.z + yr0.w + yr1.z + yr1.w;
    float qyc = yr2.x + yr2.y + yr3.x + yr3.y;
    float qyd = yr2.z + yr2.w + yr3.z + yr3.w;
    acc += (2.0f / 16384.0f) *
           (ssim_term(qxa * 0.5f, qya * 0.5f) +
            ssim_term(qxb * 0.5f, qyb * 0.5f) +
            ssim_term(qxc * 0.5f, qyc * 0.5f) +
            ssim_term(qxd * 0.5f, qyd * 0.5f));

    // d=6: this thread's full 4x4 block
    float S4x = qxa + qxb + qxc + qxd;
    float S4y = qya + qyb + qyc + qyd;
    acc += (3.0f / 4096.0f) * ssim_term(S4x * 0.25f, S4y * 0.25f);

    // d=5 via shuffles: rows 2w/2w+1 (lane +16), then col pair (lane +1)
    float ax = S4x + __shfl_down_sync(FULL, S4x, 16);
    float ay = S4y + __shfl_down_sync(FULL, S4y, 16);
    float S8x = ax + __shfl_down_sync(FULL, ax, 1);
    float S8y = ay + __shfl_down_sync(FULL, ay, 1);
    if (lane < 16 && !(lane & 1)) {
        acc += (4.0f / 1024.0f) * ssim_term(S8x * 0.125f, S8y * 0.125f);
        n8x[w * 8 + (lane >> 1)] = S8x;   // d=5 node (row=w, col=qx/2)
        n8y[w * 8 + (lane >> 1)] = S8y;
    }

    // per-warp loss reduction (deterministic xor butterfly)
    #pragma unroll
    for (int o = 16; o > 0; o >>= 1) acc += __shfl_xor_sync(FULL, acc, o);
    if (lane == 0) accW[w] = acc;

    __syncthreads();              // only CTA-wide barrier
    if (w != 0) return;           // warps 1..7 retire

    // ---- warp 0: d=4..2 from the 8x8 d=5 node grid ----
    float acc2 = 0.0f, S16x = 0.0f, S16y = 0.0f;
    if (lane < 16) {
        int ny = lane >> 2, nx = lane & 3;       // 4x4 d=4 node grid
        int b = ny * 16 + nx * 2;
        S16x = n8x[b] + n8x[b + 1] + n8x[b + 8] + n8x[b + 9];
        S16y = n8y[b] + n8y[b + 1] + n8y[b + 8] + n8y[b + 9];
        acc2 = (5.0f / 256.0f) *
               ssim_term(S16x * (1.0f / 16.0f), S16y * (1.0f / 16.0f));
    }
    if (lane < 8) acc2 += accW[lane];

    // d=3: lanes {0,2,8,10}
    float bx = S16x + __shfl_down_sync(FULL, S16x, 1);
    float by = S16y + __shfl_down_sync(FULL, S16y, 1);
    float S32x = bx + __shfl_down_sync(FULL, bx, 4);
    float S32y = by + __shfl_down_sync(FULL, by, 4);
    if (lane == 0 || lane == 2 || lane == 8 || lane == 10)
        acc2 += (6.0f / 64.0f) *
                ssim_term(S32x * (1.0f / 32.0f), S32y * (1.0f / 32.0f));

    // d=2: one node per CTA (tile total), lane 0
    float cx = S32x + __shfl_down_sync(FULL, S32x, 2);
    float cy = S32y + __shfl_down_sync(FULL, S32y, 2);
    float S64x = cx + __shfl_down_sync(FULL, cx, 8);
    float S64y = cy + __shfl_down_sync(FULL, cy, 8);
    if (lane == 0)
        acc2 += (7.0f / 16.0f) *
                ssim_term(S64x * (1.0f / 64.0f), S64y * (1.0f / 64.0f));

    #pragma unroll
    for (int o = 16; o > 0; o >>= 1) acc2 += __shfl_xor_sync(FULL, acc2, o);

    int last = 0;
    if (lane == 0) {
        g_partial[bid] = acc2;
        g_tileSx[bid]  = S64x;
        g_tileSy[bid]  = S64y;
        __threadfence();
        unsigned old = atomicAdd(&g_count, 1u);
        last = (old == 15u) ? 1 : 0;
    }
    last = __shfl_sync(FULL, last, 0);
    if (!last) return;

    // ---- finisher: warp 0 of the last-arriving CTA ----
    if (lane == 0) g_count = 0;   // reset for next graph replay

    // sum of 16 CTA partials (one per lane<16)
    float ftot = (lane < 16) ? __ldcg(&g_partial[lane]) : 0.0f;

    // d=1: 4 nodes (h=128), lanes 0..3 (parallel L2 loads)
    float S128x = 0.0f, S128y = 0.0f;
    if (lane < 4) {
        int ny = lane >> 1, nx = lane & 1;
        int b = ny * 8 + nx * 2;                 // 2ny*4 + 2nx in 4x4 tile grid
        S128x = __ldcg(&g_tileSx[b])     + __ldcg(&g_tileSx[b + 1]) +
                __ldcg(&g_tileSx[b + 4]) + __ldcg(&g_tileSx[b + 5]);
        S128y = __ldcg(&g_tileSy[b])     + __ldcg(&g_tileSy[b + 1]) +
                __ldcg(&g_tileSy[b + 4]) + __ldcg(&g_tileSy[b + 5]);
        ftot += 2.0f *
                ssim_term(S128x * (1.0f / 128.0f), S128y * (1.0f / 128.0f));
    }

    // d=0: root
    float ex = S128x + __shfl_down_sync(FULL, S128x, 1);
    float ey = S128y + __shfl_down_sync(FULL, S128y, 1);
    float S256x = ex + __shfl_down_sync(FULL, ex, 2);
    float S256y = ey + __shfl_down_sync(FULL, ey, 2);
    if (lane == 0)
        ftot += 9.0f *
                ssim_term(S256x * (1.0f / 256.0f), S256y * (1.0f / 256.0f));

    #pragma unroll
    for (int o = 16; o > 0; o >>= 1) ftot += __shfl_xor_sync(FULL, ftot, o);

    if (lane == 0) out[0] = ftot;
}

extern "C" void kernel_launch(void* const* d_in, const int* in_sizes, int n_in,
                              void* d_out, int out_size) {
    const float* x = (const float*)d_in[0];   // input  (256x256 f32)
    const float* y = (const float*)d_in[1];   // target (256x256 f32)
    float* out = (float*)d_out;               // scalar f32
    loss_quadtree_kernel<<<16, 256>>>(x, y, out);
}

// round 8
// speedup vs baseline: 1.5178x; 1.3604x over previous
#include <cuda_runtime.h>

#define FULL 0xffffffffu

// fast ssim loss term: 1 - (2 m_x m_y + c1)/(m_x^2 + m_y^2 + c1)
__device__ __forceinline__ float ssim_term(float mx, float my) {
    const float c1 = 0.2f;
    return 1.0f - __fdividef(2.0f * mx * my + c1,
                             mx * mx + my * my + c1);
}

__device__ __forceinline__ unsigned smem_u32(const void* p) {
    unsigned a;
    asm("{ .reg .u64 t; cvta.to.shared.u64 t, %1; cvt.u32.u64 %0, t; }"
        : "=r"(a) : "l"(p));
    return a;
}
__device__ __forceinline__ unsigned mapa_rank0(unsigned addr) {
    unsigned r;
    asm("mapa.shared::cluster.u32 %0, %1, 0;" : "=r"(r) : "r"(addr));
    return r;
}
__device__ __forceinline__ void st_cluster_f32(unsigned addr, float v) {
    asm volatile("st.shared::cluster.f32 [%0], %1;" :: "r"(addr), "f"(v)
                 : "memory");
}

// 16 CTAs = ONE cluster (4x4 grid of 64x64 tiles), 256 threads each.
// Thread owns a 4x4 pixel block (one d=6 node), 8 x LDG.128 up front.
// Cross-CTA combine via DSMEM into rank 0 + cluster barrier (no atomics,
// no membar.gpu, no L2 staging). Rank-0 warp 0 finishes d=1, d=0 from its
// own shared memory.
// Depth weights W_d = 0.25^d * K_LOSS[d]:
//   d=8: 1/65536  d=7: 2/16384  d=6: 3/4096  d=5: 4/1024  d=4: 5/256
//   d=3: 6/64     d=2: 7/16     d=1: 2       d=0: 9
__global__ __launch_bounds__(256, 1) __cluster_dims__(16, 1, 1)
void loss_quadtree_kernel(const float* __restrict__ x,
                          const float* __restrict__ y,
                          float* __restrict__ out) {
    __shared__ float n8x[64];   // d=5 node sums (8x8 grid per CTA)
    __shared__ float n8y[64];
    __shared__ float accW[8];   // per-warp loss partials
    __shared__ float pSx[16];   // rank 0 only: per-tile sums (DSMEM targets)
    __shared__ float pSy[16];
    __shared__ float pL[16];    // rank 0 only: per-CTA loss partials

    const int t    = threadIdx.x;
    const int lane = t & 31;
    const int w    = t >> 5;
    const int bid  = blockIdx.x;                   // == cluster rank
    const int tx   = bid & 3, ty = bid >> 2;       // tile in 4x4 grid
    const int qx   = lane & 15;                    // block col (0..15)
    const int qy   = 2 * w + (lane >> 4);          // block row (0..15)
    const int r    = ty * 64 + qy * 4;
    const int c    = tx * 64 + qx * 4;

    // 8 x LDG.128 issued up front (MLP=8)
    const float4* x4 = (const float4*)x;
    const float4* y4 = (const float4*)y;
    const int base = r * 64 + (c >> 2);            // row stride = 256/4
    float4 xr0 = x4[base],        xr1 = x4[base + 64];
    float4 xr2 = x4[base + 128],  xr3 = x4[base + 192];
    float4 yr0 = y4[base],        yr1 = y4[base + 64];
    float4 yr2 = y4[base + 128],  yr3 = y4[base + 192];

    // d=8: 16 per-pixel terms
    float s8 =
        ssim_term(xr0.x, yr0.x) + ssim_term(xr0.y, yr0.y) +
        ssim_term(xr0.z, yr0.z) + ssim_term(xr0.w, yr0.w) +
        ssim_term(xr1.x, yr1.x) + ssim_term(xr1.y, yr1.y) +
        ssim_term(xr1.z, yr1.z) + ssim_term(xr1.w, yr1.w) +
        ssim_term(xr2.x, yr2.x) + ssim_term(xr2.y, yr2.y) +
        ssim_term(xr2.z, yr2.z) + ssim_term(xr2.w, yr2.w) +
        ssim_term(xr3.x, yr3.x) + ssim_term(xr3.y, yr3.y) +
        ssim_term(xr3.z, yr3.z) + ssim_term(xr3.w, yr3.w);
    float acc = (1.0f / 65536.0f) * s8;

    // d=7: 4 quad (2x2) sums
    float qxa = xr0.x + xr0.y + xr1.x + xr1.y;
    float qxb = xr0.z + xr0.w + xr1.z + xr1.w;
    float qxc = xr2.x + xr2.y + xr3.x + xr3.y;
    float qxd = xr2.z + xr2.w + xr3.z + xr3.w;
    float qya = yr0.x + yr0.y + yr1.x + yr1.y;
    float qyb = yr0.z + yr0.w + yr1.z + yr1.w;
    float qyc = yr2.x + yr2.y + yr3.x + yr3.y;
    float qyd = yr2.z + yr2.w + yr3.z + yr3.w;
    acc += (2.0f / 16384.0f) *
           (ssim_term(qxa * 0.5f, qya * 0.5f) +
            ssim_term(qxb * 0.5f, qyb * 0.5f) +
            ssim_term(qxc * 0.5f, qyc * 0.5f) +
            ssim_term(qxd * 0.5f, qyd * 0.5f));

    // d=6: this thread's full 4x4 block
    float S4x = qxa + qxb + qxc + qxd;
    float S4y = qya + qyb + qyc + qyd;
    acc += (3.0f / 4096.0f) * ssim_term(S4x * 0.25f, S4y * 0.25f);

    // d=5 via shuffles: rows 2w/2w+1 (lane +16), then col pair (lane +1)
    float ax = S4x + __shfl_down_sync(FULL, S4x, 16);
    float ay = S4y + __shfl_down_sync(FULL, S4y, 16);
    float S8x = ax + __shfl_down_sync(FULL, ax, 1);
    float S8y = ay + __shfl_down_sync(FULL, ay, 1);
    if (lane < 16 && !(lane & 1)) {
        acc += (4.0f / 1024.0f) * ssim_term(S8x * 0.125f, S8y * 0.125f);
        n8x[w * 8 + (lane >> 1)] = S8x;
        n8y[w * 8 + (lane >> 1)] = S8y;
    }

    // per-warp loss reduction (deterministic xor butterfly)
    #pragma unroll
    for (int o = 16; o > 0; o >>= 1) acc += __shfl_xor_sync(FULL, acc, o);
    if (lane == 0) accW[w] = acc;

    __syncthreads();              // only CTA-wide barrier

    if (w == 0) {
        // ---- warp 0: d=4..2 from the 8x8 d=5 node grid ----
        float acc2 = 0.0f, S16x = 0.0f, S16y = 0.0f;
        if (lane < 16) {
            int ny = lane >> 2, nx = lane & 3;       // 4x4 d=4 node grid
            int b = ny * 16 + nx * 2;
            S16x = n8x[b] + n8x[b + 1] + n8x[b + 8] + n8x[b + 9];
            S16y = n8y[b] + n8y[b + 1] + n8y[b + 8] + n8y[b + 9];
            acc2 = (5.0f / 256.0f) *
                   ssim_term(S16x * (1.0f / 16.0f), S16y * (1.0f / 16.0f));
        }
        if (lane < 8) acc2 += accW[lane];

        // d=3: lanes {0,2,8,10}
        float bx = S16x + __shfl_down_sync(FULL, S16x, 1);
        float by = S16y + __shfl_down_sync(FULL, S16y, 1);
        float S32x = bx + __shfl_down_sync(FULL, bx, 4);
        float S32y = by + __shfl_down_sync(FULL, by, 4);
        if (lane == 0 || lane == 2 || lane == 8 || lane == 10)
            acc2 += (6.0f / 64.0f) *
                    ssim_term(S32x * (1.0f / 32.0f), S32y * (1.0f / 32.0f));

        // d=2: one node per CTA (tile total), lane 0
        float cx = S32x + __shfl_down_sync(FULL, S32x, 2);
        float cy = S32y + __shfl_down_sync(FULL, S32y, 2);
        float S64x = cx + __shfl_down_sync(FULL, cx, 8);
        float S64y = cy + __shfl_down_sync(FULL, cy, 8);
        if (lane == 0)
            acc2 += (7.0f / 16.0f) *
                    ssim_term(S64x * (1.0f / 64.0f), S64y * (1.0f / 64.0f));

        #pragma unroll
        for (int o = 16; o > 0; o >>= 1) acc2 += __shfl_xor_sync(FULL, acc2, o);

        // lane 0: publish (loss partial, tile sums) into rank 0's smem (DSMEM)
        if (lane == 0) {
            st_cluster_f32(mapa_rank0(smem_u32(&pL[bid])),  acc2);
            st_cluster_f32(mapa_rank0(smem_u32(&pSx[bid])), S64x);
            st_cluster_f32(mapa_rank0(smem_u32(&pSy[bid])), S64y);
        }
    }

    // Every thread arrives (release covers lane 0's DSMEM stores).
    asm volatile("barrier.cluster.arrive;" ::: "memory");
    if (bid != 0 || w != 0) return;

    // ---- finisher: rank 0, warp 0 ----
    asm volatile("barrier.cluster.wait;" ::: "memory");   // acquire

    float ftot = (lane < 16) ? pL[lane] : 0.0f;

    // d=1: 4 nodes (h=128), lanes 0..3, from local smem
    float S128x = 0.0f, S128y = 0.0f;
    if (lane < 4) {
        int ny = lane >> 1, nx = lane & 1;
        int b = ny * 8 + nx * 2;                 // (2ny)*4 + 2nx in 4x4 grid
        S128x = pSx[b] + pSx[b + 1] + pSx[b + 4] + pSx[b + 5];
        S128y = pSy[b] + pSy[b + 1] + pSy[b + 4] + pSy[b + 5];
        ftot += 2.0f *
                ssim_term(S128x * (1.0f / 128.0f), S128y * (1.0f / 128.0f));
    }

    // d=0: root
    float ex = S128x + __shfl_down_sync(FULL, S128x, 1);
    float ey = S128y + __shfl_down_sync(FULL, S128y, 1);
    float S256x = ex + __shfl_down_sync(FULL, ex, 2);
    float S256y = ey + __shfl_down_sync(FULL, ey, 2);
    if (lane == 0)
        ftot += 9.0f *
                ssim_term(S256x * (1.0f / 256.0f), S256y * (1.0f / 256.0f));

    #pragma unroll
    for (int o = 16; o > 0; o >>= 1) ftot += __shfl_xor_sync(FULL, ftot, o);

    if (lane == 0) out[0] = ftot;
}

extern "C" void kernel_launch(void* const* d_in, const int* in_sizes, int n_in,
                              void* d_out, int out_size) {
    const float* x = (const float*)d_in[0];   // input  (256x256 f32)
    const float* y = (const float*)d_in[1];   // target (256x256 f32)
    float* out = (float*)d_out;               // scalar f32

    // 16-CTA cluster exceeds the portable limit (8); opt in. Host-side,
    // idempotent, capture-safe (not a stream operation).
    cudaFuncSetAttribute(loss_quadtree_kernel,
                         cudaFuncAttributeNonPortableClusterSizeAllowed, 1);
    loss_quadtree_kernel<<<16, 256>>>(x, y, out);
}